// round 12
// baseline (speedup 1.0000x reference)
#include <cuda_runtime.h>
#include <math.h>

#define N_NODES 10000
#define N_EDGES 160000
#define H       128
#define F3H     384
#define E_RBF   20
#define L_LAYERS 3
#define PI_F    3.14159265358979f
#define CUTOFF_F 5.0f

#define NPB 4     // nodes per block (scalar_out / readout) — proven R5
#define NPU 4     // nodes per block (update) — proven R5
#define AGT 256   // aggregate threads (2 edge groups x 128 columns)
#define AGG 2     // edge groups
#define NGB 2     // nodes per aggregate block

// ---------- persistent scratch ----------
__device__ float g_ns  [N_NODES * H];
__device__ float g_ns2 [N_NODES * H];
__device__ float g_vecA[N_NODES * 3 * H];
__device__ float g_vecB[N_NODES * 3 * H];
__device__ float g_so  [N_NODES * F3H];

// CSR / sorted edge data (built once per launch)
__device__ int    g_rowptr[N_NODES + 1];
__device__ int    g_cursor[N_NODES];
__device__ int    g_src_s [N_EDGES];
__device__ float4 g_geo_s [N_EDGES];             // {fcut, u0, u1, u2}
__device__ float  g_rbf_s [N_EDGES * E_RBF];

__device__ __forceinline__ float silu_f(float x) {
    return x / (1.0f + expf(-x));
}

// ---------- CSR build ----------
__global__ void k_zero_cnt() {
    int i = blockIdx.x * blockDim.x + threadIdx.x;
    if (i < N_NODES) g_cursor[i] = 0;
}

__global__ void k_hist(const int* __restrict__ edge) {
    int e = blockIdx.x * blockDim.x + threadIdx.x;
    if (e < N_EDGES) atomicAdd(&g_cursor[edge[2 * e]], 1);
}

__global__ void __launch_bounds__(1024) k_scan() {
    __shared__ int s_part[1024];
    int tid = threadIdx.x;
    const int CH = 10;
    int base = tid * CH;
    int local[CH];
    int sum = 0;
#pragma unroll
    for (int i = 0; i < CH; i++) {
        int idx = base + i;
        int v = (idx < N_NODES) ? g_cursor[idx] : 0;
        local[i] = sum;
        sum += v;
    }
    s_part[tid] = sum;
    __syncthreads();
    for (int off = 1; off < 1024; off <<= 1) {
        int add = (tid >= off) ? s_part[tid - off] : 0;
        __syncthreads();
        s_part[tid] += add;
        __syncthreads();
    }
    int excl = (tid > 0) ? s_part[tid - 1] : 0;
#pragma unroll
    for (int i = 0; i < CH; i++) {
        int idx = base + i;
        if (idx < N_NODES) {
            int rp = excl + local[i];
            g_rowptr[idx] = rp;
            g_cursor[idx] = rp;
        }
    }
    if (tid == 0) g_rowptr[N_NODES] = N_EDGES;
}

__global__ void k_scatter(const int* __restrict__ edge,
                          const float* __restrict__ ediff,
                          const float* __restrict__ edist) {
    int e = blockIdx.x * blockDim.x + threadIdx.x;
    if (e >= N_EDGES) return;
    int dst = edge[2 * e], src = edge[2 * e + 1];
    int pos = atomicAdd(&g_cursor[dst], 1);
    g_src_s[pos] = src;
    float dist = edist[e];
    float fcut = (dist < CUTOFF_F) ? 0.5f * (cosf(PI_F * dist / CUTOFF_F) + 1.0f) : 0.0f;
    float inv = 1.0f / dist;
    float4 geo;
    geo.x = fcut;
    geo.y = ediff[3 * e + 0] * inv;
    geo.z = ediff[3 * e + 1] * inv;
    geo.w = ediff[3 * e + 2] * inv;
    g_geo_s[pos] = geo;
    float4* rb4 = reinterpret_cast<float4*>(g_rbf_s + (size_t)pos * E_RBF);
#pragma unroll
    for (int q = 0; q < E_RBF / 4; q++) {
        float4 v;
        v.x = sinf(dist * (float)(4 * q + 1) * (PI_F / CUTOFF_F)) * inv;
        v.y = sinf(dist * (float)(4 * q + 2) * (PI_F / CUTOFF_F)) * inv;
        v.z = sinf(dist * (float)(4 * q + 3) * (PI_F / CUTOFF_F)) * inv;
        v.w = sinf(dist * (float)(4 * q + 4) * (PI_F / CUTOFF_F)) * inv;
        rb4[q] = v;
    }
}

// ---------- init ----------
__global__ void __launch_bounds__(H) k_init(const int* __restrict__ z,
                                            const float* __restrict__ embed) {
    int i = blockIdx.x, j = threadIdx.x;
    g_ns[i * H + j] = embed[z[i] * H + j];
#pragma unroll
    for (int d = 0; d < 3; d++) g_vecA[i * 3 * H + d * H + j] = 0.0f;
}

// ---------- scalar_out (R5 exact) ----------
__global__ void __launch_bounds__(H) k_scalar_out(const float* __restrict__ W1,
                                                  const float* __restrict__ b1,
                                                  const float* __restrict__ W2,
                                                  const float* __restrict__ b2) {
    int i0 = blockIdx.x * NPB, j = threadIdx.x;
    __shared__ float s_x[NPB][H];
    __shared__ float s_h[NPB][H];
#pragma unroll
    for (int n = 0; n < NPB; n++) s_x[n][j] = g_ns[(i0 + n) * H + j];
    __syncthreads();

    float acc[NPB];
    float bb = b1[j];
#pragma unroll
    for (int n = 0; n < NPB; n++) acc[n] = bb;
    for (int k = 0; k < H; k++) {
        float w = W1[k * H + j];
#pragma unroll
        for (int n = 0; n < NPB; n++) acc[n] += s_x[n][k] * w;
    }
#pragma unroll
    for (int n = 0; n < NPB; n++) s_h[n][j] = silu_f(acc[n]);
    __syncthreads();

    float a0[NPB], a1[NPB], a2[NPB];
    float c0 = b2[j], c1 = b2[H + j], c2 = b2[2 * H + j];
#pragma unroll
    for (int n = 0; n < NPB; n++) { a0[n] = c0; a1[n] = c1; a2[n] = c2; }
    for (int k = 0; k < H; k++) {
        float w0 = W2[k * F3H + j];
        float w1 = W2[k * F3H + H + j];
        float w2 = W2[k * F3H + 2 * H + j];
#pragma unroll
        for (int n = 0; n < NPB; n++) {
            float h = s_h[n][k];
            a0[n] += h * w0; a1[n] += h * w1; a2[n] += h * w2;
        }
    }
#pragma unroll
    for (int n = 0; n < NPB; n++) {
        g_so[(i0 + n) * F3H + j]         = a0[n];
        g_so[(i0 + n) * F3H + H + j]     = a1[n];
        g_so[(i0 + n) * F3H + 2 * H + j] = a2[n];
    }
}

// ---------- aggregate v3: 2 edge-groups x 128 columns, smem combine ----------
__global__ void __launch_bounds__(AGT) k_aggregate(const float* __restrict__ Fw,
                                                   const float* __restrict__ Fb) {
    int tid = threadIdx.x;
    int j = tid & (H - 1);
    int grp = tid >> 7;               // 0..AGG-1

    // per-thread column slice of the filter weights
    float rw0[E_RBF], rw1[E_RBF], rw2[E_RBF];
#pragma unroll
    for (int k = 0; k < E_RBF; k++) {
        rw0[k] = Fw[k * F3H + j];
        rw1[k] = Fw[k * F3H + H + j];
        rw2[k] = Fw[k * F3H + 2 * H + j];
    }
    float rb0 = Fb[j], rb1 = Fb[H + j], rb2 = Fb[2 * H + j];

    __shared__ float s_red[AGG - 1][4][H];   // partials from groups > 0

    int n0 = blockIdx.x * NGB;
    for (int n = n0; n < n0 + NGB; n++) {
        int r0 = g_rowptr[n], r1 = g_rowptr[n + 1];
        float accs = 0.0f, av0 = 0.0f, av1 = 0.0f, av2 = 0.0f;
#pragma unroll 2
        for (int p = r0 + grp; p < r1; p += AGG) {
            int src = g_src_s[p];
            float4 geo = g_geo_s[p];
            const float4* rbf4 = reinterpret_cast<const float4*>(g_rbf_s + (size_t)p * E_RBF);
            float4 rA = rbf4[0], rB = rbf4[1], rC = rbf4[2], rD = rbf4[3], rE = rbf4[4];
            float rbf[E_RBF] = {rA.x, rA.y, rA.z, rA.w, rB.x, rB.y, rB.z, rB.w,
                                rC.x, rC.y, rC.z, rC.w, rD.x, rD.y, rD.z, rD.w,
                                rE.x, rE.y, rE.z, rE.w};

            float fw0 = rb0, fw1 = rb1, fw2 = rb2;
#pragma unroll
            for (int k = 0; k < E_RBF; k++) {
                fw0 += rbf[k] * rw0[k];
                fw1 += rbf[k] * rw1[k];
                fw2 += rbf[k] * rw2[k];
            }

            const float* so = g_so + (size_t)src * F3H;
            float fcut = geo.x;
            float gsv = fw0 * (fcut * so[j]);
            float gev = fw1 * (fcut * so[H + j]);
            accs += fw2 * (fcut * so[2 * H + j]);

            const float* vin = g_vecA + (size_t)src * 3 * H;
            av0 += vin[j]         * gsv + gev * geo.y;
            av1 += vin[H + j]     * gsv + gev * geo.z;
            av2 += vin[2 * H + j] * gsv + gev * geo.w;
        }

        if (grp > 0) {
            s_red[grp - 1][0][j] = accs;
            s_red[grp - 1][1][j] = av0;
            s_red[grp - 1][2][j] = av1;
            s_red[grp - 1][3][j] = av2;
        }
        __syncthreads();
        if (grp == 0) {
#pragma unroll
            for (int g = 0; g < AGG - 1; g++) {
                accs += s_red[g][0][j];
                av0  += s_red[g][1][j];
                av1  += s_red[g][2][j];
                av2  += s_red[g][3][j];
            }
            g_ns2[(size_t)n * H + j] = g_ns[(size_t)n * H + j] + accs;
            float* vo = g_vecB + (size_t)n * 3 * H;
            const float* va = g_vecA + (size_t)n * 3 * H;
            vo[j]         = va[j]         + av0;
            vo[H + j]     = va[H + j]     + av1;
            vo[2 * H + j] = va[2 * H + j] + av2;
        }
        __syncthreads();
    }
}

// ---------- update (R5 exact, NPU=4) ----------
__global__ void __launch_bounds__(H) k_update(const float* __restrict__ Uw,
                                              const float* __restrict__ Ub,
                                              const float* __restrict__ Vw,
                                              const float* __restrict__ Vb,
                                              const float* __restrict__ W1,
                                              const float* __restrict__ b1,
                                              const float* __restrict__ W2,
                                              const float* __restrict__ b2) {
    int i0 = blockIdx.x * NPU, j = threadIdx.x;
    __shared__ float s_v[NPU][3 * H];
    __shared__ float s_in[NPU][2 * H];
    __shared__ float s_h[NPU][H];

    float ns[NPU];
#pragma unroll
    for (int n = 0; n < NPU; n++) {
#pragma unroll
        for (int d = 0; d < 3; d++)
            s_v[n][d * H + j] = g_vecB[(i0 + n) * 3 * H + d * H + j];
        ns[n] = g_ns2[(i0 + n) * H + j];
        s_in[n][H + j] = ns[n];
    }
    __syncthreads();

    float Uv[NPU][3], Vv[NPU][3];
    float ub = Ub[j], vb = Vb[j];
#pragma unroll
    for (int n = 0; n < NPU; n++)
#pragma unroll
        for (int d = 0; d < 3; d++) { Uv[n][d] = ub; Vv[n][d] = vb; }

    for (int k = 0; k < H; k++) {
        float u = Uw[k * H + j];
        float v = Vw[k * H + j];
#pragma unroll
        for (int n = 0; n < NPU; n++)
#pragma unroll
            for (int d = 0; d < 3; d++) {
                float x = s_v[n][d * H + k];
                Uv[n][d] += x * u;
                Vv[n][d] += x * v;
            }
    }
#pragma unroll
    for (int n = 0; n < NPU; n++)
        s_in[n][j] = sqrtf(Vv[n][0] * Vv[n][0] + Vv[n][1] * Vv[n][1] + Vv[n][2] * Vv[n][2]);
    __syncthreads();

    float acc[NPU];
    float bb = b1[j];
#pragma unroll
    for (int n = 0; n < NPU; n++) acc[n] = bb;
    for (int k = 0; k < 2 * H; k++) {
        float w = W1[k * H + j];
#pragma unroll
        for (int n = 0; n < NPU; n++) acc[n] += s_in[n][k] * w;
    }
#pragma unroll
    for (int n = 0; n < NPU; n++) s_h[n][j] = silu_f(acc[n]);
    __syncthreads();

    float a0[NPU], a1[NPU], a2[NPU];
    float c0 = b2[j], c1 = b2[H + j], c2 = b2[2 * H + j];
#pragma unroll
    for (int n = 0; n < NPU; n++) { a0[n] = c0; a1[n] = c1; a2[n] = c2; }
    for (int k = 0; k < H; k++) {
        float w0 = W2[k * F3H + j];
        float w1 = W2[k * F3H + H + j];
        float w2 = W2[k * F3H + 2 * H + j];
#pragma unroll
        for (int n = 0; n < NPU; n++) {
            float h = s_h[n][k];
            a0[n] += h * w0; a1[n] += h * w1; a2[n] += h * w2;
        }
    }
#pragma unroll
    for (int n = 0; n < NPU; n++) {
        float dot = 0.0f;
#pragma unroll
        for (int d = 0; d < 3; d++) {
            g_vecA[(i0 + n) * 3 * H + d * H + j] = s_v[n][d * H + j] + a0[n] * Uv[n][d];
            dot += Uv[n][d] * Vv[n][d];
        }
        g_ns[(i0 + n) * H + j] = ns[n] + a1[n] * dot + a2[n];
    }
}

// ---------- readout (R5 exact) ----------
__global__ void __launch_bounds__(H) k_readout(const float* __restrict__ W1,
                                               const float* __restrict__ b1,
                                               const float* __restrict__ W2,
                                               const float* __restrict__ b2,
                                               float* __restrict__ out) {
    int i0 = blockIdx.x * NPB, j = threadIdx.x;
    __shared__ float s_x[NPB][H];
    __shared__ float s_h[NPB][H];
#pragma unroll
    for (int n = 0; n < NPB; n++) s_x[n][j] = g_ns[(i0 + n) * H + j];
    __syncthreads();

    float acc[NPB];
    float bb = b1[j];
#pragma unroll
    for (int n = 0; n < NPB; n++) acc[n] = bb;
    for (int k = 0; k < H; k++) {
        float w = W1[k * H + j];
#pragma unroll
        for (int n = 0; n < NPB; n++) acc[n] += s_x[n][k] * w;
    }
#pragma unroll
    for (int n = 0; n < NPB; n++) s_h[n][j] = silu_f(acc[n]);
    __syncthreads();

    float a[NPB];
    float c = b2[j];
#pragma unroll
    for (int n = 0; n < NPB; n++) a[n] = c;
    for (int k = 0; k < H; k++) {
        float w = W2[k * H + j];
#pragma unroll
        for (int n = 0; n < NPB; n++) a[n] += s_h[n][k] * w;
    }
#pragma unroll
    for (int n = 0; n < NPB; n++) out[(i0 + n) * H + j] = a[n];
}

// ---------- host launcher ----------
extern "C" void kernel_launch(void* const* d_in, const int* in_sizes, int n_in,
                              void* d_out, int out_size) {
    const int*   z      = (const int*)  d_in[0];
    const int*   edge   = (const int*)  d_in[1];
    const float* ediff  = (const float*)d_in[2];
    const float* edist  = (const float*)d_in[3];
    const float* embed  = (const float*)d_in[4];
    const float* mfw    = (const float*)d_in[5];
    const float* mfb    = (const float*)d_in[6];
    const float* mw1    = (const float*)d_in[7];
    const float* mb1    = (const float*)d_in[8];
    const float* mw2    = (const float*)d_in[9];
    const float* mb2    = (const float*)d_in[10];
    const float* uUw    = (const float*)d_in[11];
    const float* uUb    = (const float*)d_in[12];
    const float* uVw    = (const float*)d_in[13];
    const float* uVb    = (const float*)d_in[14];
    const float* uw1    = (const float*)d_in[15];
    const float* ub1    = (const float*)d_in[16];
    const float* uw2    = (const float*)d_in[17];
    const float* ub2    = (const float*)d_in[18];
    const float* row1   = (const float*)d_in[19];
    const float* rob1   = (const float*)d_in[20];
    const float* row2   = (const float*)d_in[21];
    const float* rob2   = (const float*)d_in[22];
    float* out = (float*)d_out;

    k_zero_cnt<<<(N_NODES + 255) / 256, 256>>>();
    k_hist<<<(N_EDGES + 255) / 256, 256>>>(edge);
    k_scan<<<1, 1024>>>();
    k_scatter<<<(N_EDGES + 255) / 256, 256>>>(edge, ediff, edist);

    k_init<<<N_NODES, H>>>(z, embed);

    for (int l = 0; l < L_LAYERS; l++) {
        k_scalar_out<<<N_NODES / NPB, H>>>(mw1 + l * H * H, mb1 + l * H,
                                           mw2 + l * H * F3H, mb2 + l * F3H);
        k_aggregate<<<N_NODES / NGB, AGT>>>(mfw + l * E_RBF * F3H, mfb + l * F3H);
        k_update<<<N_NODES / NPU, H>>>(uUw + l * H * H, uUb + l * H,
                                       uVw + l * H * H, uVb + l * H,
                                       uw1 + l * 2 * H * H, ub1 + l * H,
                                       uw2 + l * H * F3H, ub2 + l * F3H);
    }
    k_readout<<<N_NODES / NPB, H>>>(row1, rob1, row2, rob2, out);
}

// round 14
// speedup vs baseline: 1.1750x; 1.1750x over previous
#include <cuda_runtime.h>
#include <math.h>

#define N_NODES 10000
#define N_EDGES 160000
#define H       128
#define F3H     384
#define E_RBF   20
#define L_LAYERS 3
#define PI_F    3.14159265358979f
#define CUTOFF_F 5.0f

#define NPB 4     // nodes per block (scalar_out / readout) — proven R5
#define NPU 4     // nodes per block (update) — proven R5
#define EPB 16    // edges per block (edge kernel)

// ---------- persistent scratch ----------
__device__ float g_ns  [N_NODES * H];        // node_scalar (atomics accumulate msg_s here)
__device__ float g_vecA[N_NODES * 3 * H];    // node_vector (pre-aggregation / post-update)
__device__ float g_vecB[N_NODES * 3 * H];    // node_vector (aggregation target)
__device__ float g_so  [N_NODES * F3H];      // scalar_out

// edge-order precomputed geometry (built once per launch)
__device__ float4 g_geo [N_EDGES];           // {fcut, u0, u1, u2}
__device__ float  g_rbf [N_EDGES * E_RBF];

__device__ __forceinline__ float silu_f(float x) {
    return x / (1.0f + expf(-x));
}

// ---------- prep: rbf/fcut/unit in EDGE order (no sort, no atomics) ----------
__global__ void k_prep(const float* __restrict__ ediff,
                       const float* __restrict__ edist) {
    int e = blockIdx.x * blockDim.x + threadIdx.x;
    if (e >= N_EDGES) return;
    float dist = edist[e];
    float fcut = (dist < CUTOFF_F) ? 0.5f * (cosf(PI_F * dist / CUTOFF_F) + 1.0f) : 0.0f;
    float inv = 1.0f / dist;
    float4 geo;
    geo.x = fcut;
    geo.y = ediff[3 * e + 0] * inv;
    geo.z = ediff[3 * e + 1] * inv;
    geo.w = ediff[3 * e + 2] * inv;
    g_geo[e] = geo;
    float4* rb4 = reinterpret_cast<float4*>(g_rbf + (size_t)e * E_RBF);
#pragma unroll
    for (int q = 0; q < E_RBF / 4; q++) {
        float4 v;
        v.x = sinf(dist * (float)(4 * q + 1) * (PI_F / CUTOFF_F)) * inv;
        v.y = sinf(dist * (float)(4 * q + 2) * (PI_F / CUTOFF_F)) * inv;
        v.z = sinf(dist * (float)(4 * q + 3) * (PI_F / CUTOFF_F)) * inv;
        v.w = sinf(dist * (float)(4 * q + 4) * (PI_F / CUTOFF_F)) * inv;
        rb4[q] = v;
    }
}

// ---------- init ----------
__global__ void __launch_bounds__(H) k_init(const int* __restrict__ z,
                                            const float* __restrict__ embed) {
    int i = blockIdx.x, j = threadIdx.x;
    g_ns[i * H + j] = embed[z[i] * H + j];
#pragma unroll
    for (int d = 0; d < 3; d++) g_vecA[i * 3 * H + d * H + j] = 0.0f;
}

// ---------- vecB = vecA ----------
__global__ void k_copy_vec() {
    int idx = blockIdx.x * blockDim.x + threadIdx.x;
    const float4* src = reinterpret_cast<const float4*>(g_vecA);
    float4* dst = reinterpret_cast<float4*>(g_vecB);
    if (idx < N_NODES * 3 * H / 4) dst[idx] = src[idx];
}

// ---------- scalar_out (R5 exact) ----------
__global__ void __launch_bounds__(H) k_scalar_out(const float* __restrict__ W1,
                                                  const float* __restrict__ b1,
                                                  const float* __restrict__ W2,
                                                  const float* __restrict__ b2) {
    int i0 = blockIdx.x * NPB, j = threadIdx.x;
    __shared__ float s_x[NPB][H];
    __shared__ float s_h[NPB][H];
#pragma unroll
    for (int n = 0; n < NPB; n++) s_x[n][j] = g_ns[(i0 + n) * H + j];
    __syncthreads();

    float acc[NPB];
    float bb = b1[j];
#pragma unroll
    for (int n = 0; n < NPB; n++) acc[n] = bb;
    for (int k = 0; k < H; k++) {
        float w = W1[k * H + j];
#pragma unroll
        for (int n = 0; n < NPB; n++) acc[n] += s_x[n][k] * w;
    }
#pragma unroll
    for (int n = 0; n < NPB; n++) s_h[n][j] = silu_f(acc[n]);
    __syncthreads();

    float a0[NPB], a1[NPB], a2[NPB];
    float c0 = b2[j], c1 = b2[H + j], c2 = b2[2 * H + j];
#pragma unroll
    for (int n = 0; n < NPB; n++) { a0[n] = c0; a1[n] = c1; a2[n] = c2; }
    for (int k = 0; k < H; k++) {
        float w0 = W2[k * F3H + j];
        float w1 = W2[k * F3H + H + j];
        float w2 = W2[k * F3H + 2 * H + j];
#pragma unroll
        for (int n = 0; n < NPB; n++) {
            float h = s_h[n][k];
            a0[n] += h * w0; a1[n] += h * w1; a2[n] += h * w2;
        }
    }
#pragma unroll
    for (int n = 0; n < NPB; n++) {
        g_so[(i0 + n) * F3H + j]         = a0[n];
        g_so[(i0 + n) * F3H + H + j]     = a1[n];
        g_so[(i0 + n) * F3H + 2 * H + j] = a2[n];
    }
}

// ---------- edge kernel v2: edge-parallel, register weights, scalar RED ----------
__global__ void __launch_bounds__(H) k_edge2(const int* __restrict__ edge,
                                             const float* __restrict__ Fw,
                                             const float* __restrict__ Fb) {
    int j = threadIdx.x;

    // per-thread column slice of the filter weights (once per block)
    float rw0[E_RBF], rw1[E_RBF], rw2[E_RBF];
#pragma unroll
    for (int k = 0; k < E_RBF; k++) {
        rw0[k] = Fw[k * F3H + j];
        rw1[k] = Fw[k * F3H + H + j];
        rw2[k] = Fw[k * F3H + 2 * H + j];
    }
    float rb0 = Fb[j], rb1 = Fb[H + j], rb2 = Fb[2 * H + j];

    int e0 = blockIdx.x * EPB;
#pragma unroll 2
    for (int e = e0; e < e0 + EPB; e++) {
        int dst = edge[2 * e];
        int src = edge[2 * e + 1];
        float4 geo = g_geo[e];
        const float4* rbf4 = reinterpret_cast<const float4*>(g_rbf + (size_t)e * E_RBF);
        float4 rA = rbf4[0], rB = rbf4[1], rC = rbf4[2], rD = rbf4[3], rE = rbf4[4];
        float rbf[E_RBF] = {rA.x, rA.y, rA.z, rA.w, rB.x, rB.y, rB.z, rB.w,
                            rC.x, rC.y, rC.z, rC.w, rD.x, rD.y, rD.z, rD.w,
                            rE.x, rE.y, rE.z, rE.w};

        float fw0 = rb0, fw1 = rb1, fw2 = rb2;
#pragma unroll
        for (int k = 0; k < E_RBF; k++) {
            fw0 += rbf[k] * rw0[k];
            fw1 += rbf[k] * rw1[k];
            fw2 += rbf[k] * rw2[k];
        }

        const float* so = g_so + (size_t)src * F3H;
        float fcut = geo.x;
        float gsv = fw0 * (fcut * so[j]);
        float gev = fw1 * (fcut * so[H + j]);
        float ms  = fw2 * (fcut * so[2 * H + j]);

        atomicAdd(&g_ns[(size_t)dst * H + j], ms);

        const float* vin = g_vecA + (size_t)src * 3 * H;
        float* vout = g_vecB + (size_t)dst * 3 * H;
        atomicAdd(&vout[j],         vin[j]         * gsv + gev * geo.y);
        atomicAdd(&vout[H + j],     vin[H + j]     * gsv + gev * geo.z);
        atomicAdd(&vout[2 * H + j], vin[2 * H + j] * gsv + gev * geo.w);
    }
}

// ---------- update (R5 exact structure; reads g_ns/g_vecB, writes g_vecA/g_ns) ----------
__global__ void __launch_bounds__(H) k_update(const float* __restrict__ Uw,
                                              const float* __restrict__ Ub,
                                              const float* __restrict__ Vw,
                                              const float* __restrict__ Vb,
                                              const float* __restrict__ W1,
                                              const float* __restrict__ b1,
                                              const float* __restrict__ W2,
                                              const float* __restrict__ b2) {
    int i0 = blockIdx.x * NPU, j = threadIdx.x;
    __shared__ float s_v[NPU][3 * H];
    __shared__ float s_in[NPU][2 * H];
    __shared__ float s_h[NPU][H];

    float ns[NPU];
#pragma unroll
    for (int n = 0; n < NPU; n++) {
#pragma unroll
        for (int d = 0; d < 3; d++)
            s_v[n][d * H + j] = g_vecB[(i0 + n) * 3 * H + d * H + j];
        ns[n] = g_ns[(i0 + n) * H + j];
        s_in[n][H + j] = ns[n];
    }
    __syncthreads();

    float Uv[NPU][3], Vv[NPU][3];
    float ub = Ub[j], vb = Vb[j];
#pragma unroll
    for (int n = 0; n < NPU; n++)
#pragma unroll
        for (int d = 0; d < 3; d++) { Uv[n][d] = ub; Vv[n][d] = vb; }

    for (int k = 0; k < H; k++) {
        float u = Uw[k * H + j];
        float v = Vw[k * H + j];
#pragma unroll
        for (int n = 0; n < NPU; n++)
#pragma unroll
            for (int d = 0; d < 3; d++) {
                float x = s_v[n][d * H + k];
                Uv[n][d] += x * u;
                Vv[n][d] += x * v;
            }
    }
#pragma unroll
    for (int n = 0; n < NPU; n++)
        s_in[n][j] = sqrtf(Vv[n][0] * Vv[n][0] + Vv[n][1] * Vv[n][1] + Vv[n][2] * Vv[n][2]);
    __syncthreads();

    float acc[NPU];
    float bb = b1[j];
#pragma unroll
    for (int n = 0; n < NPU; n++) acc[n] = bb;
    for (int k = 0; k < 2 * H; k++) {
        float w = W1[k * H + j];
#pragma unroll
        for (int n = 0; n < NPU; n++) acc[n] += s_in[n][k] * w;
    }
#pragma unroll
    for (int n = 0; n < NPU; n++) s_h[n][j] = silu_f(acc[n]);
    __syncthreads();

    float a0[NPU], a1[NPU], a2[NPU];
    float c0 = b2[j], c1 = b2[H + j], c2 = b2[2 * H + j];
#pragma unroll
    for (int n = 0; n < NPU; n++) { a0[n] = c0; a1[n] = c1; a2[n] = c2; }
    for (int k = 0; k < H; k++) {
        float w0 = W2[k * F3H + j];
        float w1 = W2[k * F3H + H + j];
        float w2 = W2[k * F3H + 2 * H + j];
#pragma unroll
        for (int n = 0; n < NPU; n++) {
            float h = s_h[n][k];
            a0[n] += h * w0; a1[n] += h * w1; a2[n] += h * w2;
        }
    }
#pragma unroll
    for (int n = 0; n < NPU; n++) {
        float dot = 0.0f;
#pragma unroll
        for (int d = 0; d < 3; d++) {
            g_vecA[(i0 + n) * 3 * H + d * H + j] = s_v[n][d * H + j] + a0[n] * Uv[n][d];
            dot += Uv[n][d] * Vv[n][d];
        }
        g_ns[(i0 + n) * H + j] = ns[n] + a1[n] * dot + a2[n];
    }
}

// ---------- readout (R5 exact) ----------
__global__ void __launch_bounds__(H) k_readout(const float* __restrict__ W1,
                                               const float* __restrict__ b1,
                                               const float* __restrict__ W2,
                                               const float* __restrict__ b2,
                                               float* __restrict__ out) {
    int i0 = blockIdx.x * NPB, j = threadIdx.x;
    __shared__ float s_x[NPB][H];
    __shared__ float s_h[NPB][H];
#pragma unroll
    for (int n = 0; n < NPB; n++) s_x[n][j] = g_ns[(i0 + n) * H + j];
    __syncthreads();

    float acc[NPB];
    float bb = b1[j];
#pragma unroll
    for (int n = 0; n < NPB; n++) acc[n] = bb;
    for (int k = 0; k < H; k++) {
        float w = W1[k * H + j];
#pragma unroll
        for (int n = 0; n < NPB; n++) acc[n] += s_x[n][k] * w;
    }
#pragma unroll
    for (int n = 0; n < NPB; n++) s_h[n][j] = silu_f(acc[n]);
    __syncthreads();

    float a[NPB];
    float c = b2[j];
#pragma unroll
    for (int n = 0; n < NPB; n++) a[n] = c;
    for (int k = 0; k < H; k++) {
        float w = W2[k * H + j];
#pragma unroll
        for (int n = 0; n < NPB; n++) a[n] += s_h[n][k] * w;
    }
#pragma unroll
    for (int n = 0; n < NPB; n++) out[(i0 + n) * H + j] = a[n];
}

// ---------- host launcher ----------
extern "C" void kernel_launch(void* const* d_in, const int* in_sizes, int n_in,
                              void* d_out, int out_size) {
    const int*   z      = (const int*)  d_in[0];
    const int*   edge   = (const int*)  d_in[1];
    const float* ediff  = (const float*)d_in[2];
    const float* edist  = (const float*)d_in[3];
    const float* embed  = (const float*)d_in[4];
    const float* mfw    = (const float*)d_in[5];
    const float* mfb    = (const float*)d_in[6];
    const float* mw1    = (const float*)d_in[7];
    const float* mb1    = (const float*)d_in[8];
    const float* mw2    = (const float*)d_in[9];
    const float* mb2    = (const float*)d_in[10];
    const float* uUw    = (const float*)d_in[11];
    const float* uUb    = (const float*)d_in[12];
    const float* uVw    = (const float*)d_in[13];
    const float* uVb    = (const float*)d_in[14];
    const float* uw1    = (const float*)d_in[15];
    const float* ub1    = (const float*)d_in[16];
    const float* uw2    = (const float*)d_in[17];
    const float* ub2    = (const float*)d_in[18];
    const float* row1   = (const float*)d_in[19];
    const float* rob1   = (const float*)d_in[20];
    const float* row2   = (const float*)d_in[21];
    const float* rob2   = (const float*)d_in[22];
    float* out = (float*)d_out;

    k_prep<<<(N_EDGES + 255) / 256, 256>>>(ediff, edist);
    k_init<<<N_NODES, H>>>(z, embed);

    int copy_threads = N_NODES * 3 * H / 4;
    for (int l = 0; l < L_LAYERS; l++) {
        k_scalar_out<<<N_NODES / NPB, H>>>(mw1 + l * H * H, mb1 + l * H,
                                           mw2 + l * H * F3H, mb2 + l * F3H);
        k_copy_vec<<<(copy_threads + 255) / 256, 256>>>();
        k_edge2<<<N_EDGES / EPB, H>>>(edge, mfw + l * E_RBF * F3H, mfb + l * F3H);
        k_update<<<N_NODES / NPU, H>>>(uUw + l * H * H, uUb + l * H,
                                       uVw + l * H * H, uVb + l * H,
                                       uw1 + l * 2 * H * H, ub1 + l * H,
                                       uw2 + l * H * F3H, ub2 + l * F3H);
    }
    k_readout<<<N_NODES / NPB, H>>>(row1, rob1, row2, rob2, out);
}

// round 15
// speedup vs baseline: 1.1831x; 1.0069x over previous
#include <cuda_runtime.h>
#include <math.h>

#define N_NODES 10000
#define N_EDGES 160000
#define H       128
#define F3H     384
#define E_RBF   20
#define L_LAYERS 3
#define PI_F    3.14159265358979f
#define CUTOFF_F 5.0f

#define NPB 4     // nodes per block (scalar_out / readout)
#define NPU 4     // nodes per block (fused agg+update)

// ---------- persistent scratch (ping-pong) ----------
__device__ float g_ns0 [N_NODES * H];
__device__ float g_ns1 [N_NODES * H];
__device__ float g_vec0[N_NODES * 3 * H];
__device__ float g_vec1[N_NODES * 3 * H];
__device__ float g_so  [N_NODES * F3H];

// CSR / sorted edge data (built once per launch)
__device__ int    g_rowptr[N_NODES + 1];
__device__ int    g_cursor[N_NODES];
__device__ int    g_src_s [N_EDGES];
__device__ float4 g_geo_s [N_EDGES];             // {fcut, u0, u1, u2}
__device__ float  g_rbf_s [N_EDGES * E_RBF];

__device__ __forceinline__ float silu_f(float x) {
    return x / (1.0f + expf(-x));
}

// ---------- CSR build ----------
__global__ void k_zero_cnt() {
    int i = blockIdx.x * blockDim.x + threadIdx.x;
    if (i < N_NODES) g_cursor[i] = 0;
}

__global__ void k_hist(const int* __restrict__ edge) {
    int e = blockIdx.x * blockDim.x + threadIdx.x;
    if (e < N_EDGES) atomicAdd(&g_cursor[edge[2 * e]], 1);
}

__global__ void __launch_bounds__(1024) k_scan() {
    __shared__ int s_part[1024];
    int tid = threadIdx.x;
    const int CH = 10;
    int base = tid * CH;
    int local[CH];
    int sum = 0;
#pragma unroll
    for (int i = 0; i < CH; i++) {
        int idx = base + i;
        int v = (idx < N_NODES) ? g_cursor[idx] : 0;
        local[i] = sum;
        sum += v;
    }
    s_part[tid] = sum;
    __syncthreads();
    for (int off = 1; off < 1024; off <<= 1) {
        int add = (tid >= off) ? s_part[tid - off] : 0;
        __syncthreads();
        s_part[tid] += add;
        __syncthreads();
    }
    int excl = (tid > 0) ? s_part[tid - 1] : 0;
#pragma unroll
    for (int i = 0; i < CH; i++) {
        int idx = base + i;
        if (idx < N_NODES) {
            int rp = excl + local[i];
            g_rowptr[idx] = rp;
            g_cursor[idx] = rp;
        }
    }
    if (tid == 0) g_rowptr[N_NODES] = N_EDGES;
}

__global__ void k_scatter(const int* __restrict__ edge,
                          const float* __restrict__ ediff,
                          const float* __restrict__ edist) {
    int e = blockIdx.x * blockDim.x + threadIdx.x;
    if (e >= N_EDGES) return;
    int dst = edge[2 * e], src = edge[2 * e + 1];
    int pos = atomicAdd(&g_cursor[dst], 1);
    g_src_s[pos] = src;
    float dist = edist[e];
    float fcut = (dist < CUTOFF_F) ? 0.5f * (cosf(PI_F * dist / CUTOFF_F) + 1.0f) : 0.0f;
    float inv = 1.0f / dist;
    float4 geo;
    geo.x = fcut;
    geo.y = ediff[3 * e + 0] * inv;
    geo.z = ediff[3 * e + 1] * inv;
    geo.w = ediff[3 * e + 2] * inv;
    g_geo_s[pos] = geo;
    float4* rb4 = reinterpret_cast<float4*>(g_rbf_s + (size_t)pos * E_RBF);
#pragma unroll
    for (int q = 0; q < E_RBF / 4; q++) {
        float4 v;
        v.x = sinf(dist * (float)(4 * q + 1) * (PI_F / CUTOFF_F)) * inv;
        v.y = sinf(dist * (float)(4 * q + 2) * (PI_F / CUTOFF_F)) * inv;
        v.z = sinf(dist * (float)(4 * q + 3) * (PI_F / CUTOFF_F)) * inv;
        v.w = sinf(dist * (float)(4 * q + 4) * (PI_F / CUTOFF_F)) * inv;
        rb4[q] = v;
    }
}

// ---------- init: ns0 = embed[z], vec0 = 0 ----------
__global__ void __launch_bounds__(H) k_init(const int* __restrict__ z,
                                            const float* __restrict__ embed) {
    int i = blockIdx.x, j = threadIdx.x;
    g_ns0[i * H + j] = embed[z[i] * H + j];
#pragma unroll
    for (int d = 0; d < 3; d++) g_vec0[i * 3 * H + d * H + j] = 0.0f;
}

// ---------- scalar_out (R5 exact loops; sel chooses ns buffer) ----------
__global__ void __launch_bounds__(H) k_scalar_out(int sel,
                                                  const float* __restrict__ W1,
                                                  const float* __restrict__ b1,
                                                  const float* __restrict__ W2,
                                                  const float* __restrict__ b2) {
    const float* nsIn = sel ? g_ns1 : g_ns0;
    int i0 = blockIdx.x * NPB, j = threadIdx.x;
    __shared__ float s_x[NPB][H];
    __shared__ float s_h[NPB][H];
#pragma unroll
    for (int n = 0; n < NPB; n++) s_x[n][j] = nsIn[(i0 + n) * H + j];
    __syncthreads();

    float acc[NPB];
    float bb = b1[j];
#pragma unroll
    for (int n = 0; n < NPB; n++) acc[n] = bb;
    for (int k = 0; k < H; k++) {
        float w = W1[k * H + j];
#pragma unroll
        for (int n = 0; n < NPB; n++) acc[n] += s_x[n][k] * w;
    }
#pragma unroll
    for (int n = 0; n < NPB; n++) s_h[n][j] = silu_f(acc[n]);
    __syncthreads();

    float a0[NPB], a1[NPB], a2[NPB];
    float c0 = b2[j], c1 = b2[H + j], c2 = b2[2 * H + j];
#pragma unroll
    for (int n = 0; n < NPB; n++) { a0[n] = c0; a1[n] = c1; a2[n] = c2; }
    for (int k = 0; k < H; k++) {
        float w0 = W2[k * F3H + j];
        float w1 = W2[k * F3H + H + j];
        float w2 = W2[k * F3H + 2 * H + j];
#pragma unroll
        for (int n = 0; n < NPB; n++) {
            float h = s_h[n][k];
            a0[n] += h * w0; a1[n] += h * w1; a2[n] += h * w2;
        }
    }
#pragma unroll
    for (int n = 0; n < NPB; n++) {
        g_so[(i0 + n) * F3H + j]         = a0[n];
        g_so[(i0 + n) * F3H + H + j]     = a1[n];
        g_so[(i0 + n) * F3H + 2 * H + j] = a2[n];
    }
}

// ---------- fused aggregate + update ----------
// sel=0: nsIn=ns0, vecIn=vec0, nsOut=ns1, vecOut=vec1 ; sel=1: swapped.
__global__ void __launch_bounds__(H) k_agg_update(int sel,
                                                  const float* __restrict__ Fw,
                                                  const float* __restrict__ Fb,
                                                  const float* __restrict__ Uw,
                                                  const float* __restrict__ Ub,
                                                  const float* __restrict__ Vw,
                                                  const float* __restrict__ Vb,
                                                  const float* __restrict__ W1,
                                                  const float* __restrict__ b1,
                                                  const float* __restrict__ W2,
                                                  const float* __restrict__ b2) {
    const float* nsIn  = sel ? g_ns1  : g_ns0;
    float*       nsOut = sel ? g_ns0  : g_ns1;
    const float* vecIn = sel ? g_vec1 : g_vec0;
    float*       vecOut= sel ? g_vec0 : g_vec1;

    int i0 = blockIdx.x * NPU, j = threadIdx.x;
    __shared__ float s_v[NPU][3 * H];
    __shared__ float s_in[NPU][2 * H];
    __shared__ float s_h[NPU][H];

    // ===== Stage A: aggregation (R5 inner loop, unroll 4) =====
    {
        float rw0[E_RBF], rw1[E_RBF], rw2[E_RBF];
#pragma unroll
        for (int k = 0; k < E_RBF; k++) {
            rw0[k] = Fw[k * F3H + j];
            rw1[k] = Fw[k * F3H + H + j];
            rw2[k] = Fw[k * F3H + 2 * H + j];
        }
        float rb0 = Fb[j], rb1 = Fb[H + j], rb2 = Fb[2 * H + j];

#pragma unroll 1
        for (int n = 0; n < NPU; n++) {
            int node = i0 + n;
            int r0 = g_rowptr[node], r1 = g_rowptr[node + 1];
            float accs = 0.0f, av0 = 0.0f, av1 = 0.0f, av2 = 0.0f;
#pragma unroll 4
            for (int p = r0; p < r1; p++) {
                int src = g_src_s[p];
                float4 geo = g_geo_s[p];
                const float4* rbf4 = reinterpret_cast<const float4*>(g_rbf_s + (size_t)p * E_RBF);
                float4 rA = rbf4[0], rB = rbf4[1], rC = rbf4[2], rD = rbf4[3], rE = rbf4[4];
                float rbf[E_RBF] = {rA.x, rA.y, rA.z, rA.w, rB.x, rB.y, rB.z, rB.w,
                                    rC.x, rC.y, rC.z, rC.w, rD.x, rD.y, rD.z, rD.w,
                                    rE.x, rE.y, rE.z, rE.w};

                float fw0 = rb0, fw1 = rb1, fw2 = rb2;
#pragma unroll
                for (int k = 0; k < E_RBF; k++) {
                    fw0 += rbf[k] * rw0[k];
                    fw1 += rbf[k] * rw1[k];
                    fw2 += rbf[k] * rw2[k];
                }

                const float* so = g_so + (size_t)src * F3H;
                float fcut = geo.x;
                float gsv = fw0 * (fcut * so[j]);
                float gev = fw1 * (fcut * so[H + j]);
                accs += fw2 * (fcut * so[2 * H + j]);

                const float* vin = vecIn + (size_t)src * 3 * H;
                av0 += vin[j]         * gsv + gev * geo.y;
                av1 += vin[H + j]     * gsv + gev * geo.z;
                av2 += vin[2 * H + j] * gsv + gev * geo.w;
            }
            const float* va = vecIn + (size_t)node * 3 * H;
            s_v[n][j]         = va[j]         + av0;
            s_v[n][H + j]     = va[H + j]     + av1;
            s_v[n][2 * H + j] = va[2 * H + j] + av2;
            s_in[n][H + j] = nsIn[(size_t)node * H + j] + accs;
        }
    }
    __syncthreads();

    // ===== Stage B: update (R5 exact loops) =====
    float Uv[NPU][3], Vv[NPU][3];
    float ub = Ub[j], vb = Vb[j];
#pragma unroll
    for (int n = 0; n < NPU; n++)
#pragma unroll
        for (int d = 0; d < 3; d++) { Uv[n][d] = ub; Vv[n][d] = vb; }

    for (int k = 0; k < H; k++) {
        float u = Uw[k * H + j];
        float v = Vw[k * H + j];
#pragma unroll
        for (int n = 0; n < NPU; n++)
#pragma unroll
            for (int d = 0; d < 3; d++) {
                float x = s_v[n][d * H + k];
                Uv[n][d] += x * u;
                Vv[n][d] += x * v;
            }
    }
#pragma unroll
    for (int n = 0; n < NPU; n++)
        s_in[n][j] = sqrtf(Vv[n][0] * Vv[n][0] + Vv[n][1] * Vv[n][1] + Vv[n][2] * Vv[n][2]);
    __syncthreads();

    float acc[NPU];
    float bb = b1[j];
#pragma unroll
    for (int n = 0; n < NPU; n++) acc[n] = bb;
    for (int k = 0; k < 2 * H; k++) {
        float w = W1[k * H + j];
#pragma unroll
        for (int n = 0; n < NPU; n++) acc[n] += s_in[n][k] * w;
    }
#pragma unroll
    for (int n = 0; n < NPU; n++) s_h[n][j] = silu_f(acc[n]);
    __syncthreads();

    float a0[NPU], a1[NPU], a2[NPU];
    float c0 = b2[j], c1 = b2[H + j], c2 = b2[2 * H + j];
#pragma unroll
    for (int n = 0; n < NPU; n++) { a0[n] = c0; a1[n] = c1; a2[n] = c2; }
    for (int k = 0; k < H; k++) {
        float w0 = W2[k * F3H + j];
        float w1 = W2[k * F3H + H + j];
        float w2 = W2[k * F3H + 2 * H + j];
#pragma unroll
        for (int n = 0; n < NPU; n++) {
            float h = s_h[n][k];
            a0[n] += h * w0; a1[n] += h * w1; a2[n] += h * w2;
        }
    }
#pragma unroll
    for (int n = 0; n < NPU; n++) {
        float dot = 0.0f;
#pragma unroll
        for (int d = 0; d < 3; d++) {
            float uv = Uv[n][d];
            vecOut[(size_t)(i0 + n) * 3 * H + d * H + j] = s_v[n][d * H + j] + a0[n] * uv;
            dot += uv * Vv[n][d];
        }
        nsOut[(size_t)(i0 + n) * H + j] = s_in[n][H + j] + a1[n] * dot + a2[n];
    }
}

// ---------- readout (reads ns1 — final buffer after 3 layers) ----------
__global__ void __launch_bounds__(H) k_readout(const float* __restrict__ W1,
                                               const float* __restrict__ b1,
                                               const float* __restrict__ W2,
                                               const float* __restrict__ b2,
                                               float* __restrict__ out) {
    int i0 = blockIdx.x * NPB, j = threadIdx.x;
    __shared__ float s_x[NPB][H];
    __shared__ float s_h[NPB][H];
#pragma unroll
    for (int n = 0; n < NPB; n++) s_x[n][j] = g_ns1[(i0 + n) * H + j];
    __syncthreads();

    float acc[NPB];
    float bb = b1[j];
#pragma unroll
    for (int n = 0; n < NPB; n++) acc[n] = bb;
    for (int k = 0; k < H; k++) {
        float w = W1[k * H + j];
#pragma unroll
        for (int n = 0; n < NPB; n++) acc[n] += s_x[n][k] * w;
    }
#pragma unroll
    for (int n = 0; n < NPB; n++) s_h[n][j] = silu_f(acc[n]);
    __syncthreads();

    float a[NPB];
    float c = b2[j];
#pragma unroll
    for (int n = 0; n < NPB; n++) a[n] = c;
    for (int k = 0; k < H; k++) {
        float w = W2[k * H + j];
#pragma unroll
        for (int n = 0; n < NPB; n++) a[n] += s_h[n][k] * w;
    }
#pragma unroll
    for (int n = 0; n < NPB; n++) out[(i0 + n) * H + j] = a[n];
}

// ---------- host launcher ----------
extern "C" void kernel_launch(void* const* d_in, const int* in_sizes, int n_in,
                              void* d_out, int out_size) {
    const int*   z      = (const int*)  d_in[0];
    const int*   edge   = (const int*)  d_in[1];
    const float* ediff  = (const float*)d_in[2];
    const float* edist  = (const float*)d_in[3];
    const float* embed  = (const float*)d_in[4];
    const float* mfw    = (const float*)d_in[5];
    const float* mfb    = (const float*)d_in[6];
    const float* mw1    = (const float*)d_in[7];
    const float* mb1    = (const float*)d_in[8];
    const float* mw2    = (const float*)d_in[9];
    const float* mb2    = (const float*)d_in[10];
    const float* uUw    = (const float*)d_in[11];
    const float* uUb    = (const float*)d_in[12];
    const float* uVw    = (const float*)d_in[13];
    const float* uVb    = (const float*)d_in[14];
    const float* uw1    = (const float*)d_in[15];
    const float* ub1    = (const float*)d_in[16];
    const float* uw2    = (const float*)d_in[17];
    const float* ub2    = (const float*)d_in[18];
    const float* row1   = (const float*)d_in[19];
    const float* rob1   = (const float*)d_in[20];
    const float* row2   = (const float*)d_in[21];
    const float* rob2   = (const float*)d_in[22];
    float* out = (float*)d_out;

    k_zero_cnt<<<(N_NODES + 255) / 256, 256>>>();
    k_hist<<<(N_EDGES + 255) / 256, 256>>>(edge);
    k_scan<<<1, 1024>>>();
    k_scatter<<<(N_EDGES + 255) / 256, 256>>>(edge, ediff, edist);

    k_init<<<N_NODES, H>>>(z, embed);

    for (int l = 0; l < L_LAYERS; l++) {
        int sel = l & 1;
        k_scalar_out<<<N_NODES / NPB, H>>>(sel,
                                           mw1 + l * H * H, mb1 + l * H,
                                           mw2 + l * H * F3H, mb2 + l * F3H);
        k_agg_update<<<N_NODES / NPU, H>>>(sel,
                                           mfw + l * E_RBF * F3H, mfb + l * F3H,
                                           uUw + l * H * H, uUb + l * H,
                                           uVw + l * H * H, uVb + l * H,
                                           uw1 + l * 2 * H * H, ub1 + l * H,
                                           uw2 + l * H * F3H, ub2 + l * F3H);
    }
    k_readout<<<N_NODES / NPB, H>>>(row1, rob1, row2, rob2, out);
}

// round 16
// speedup vs baseline: 1.7199x; 1.4537x over previous
#include <cuda_runtime.h>
#include <math.h>

#define N_NODES 10000
#define N_EDGES 160000
#define H       128
#define F3H     384
#define E_RBF   20
#define L_LAYERS 3
#define PI_F    3.14159265358979f
#define CUTOFF_F 5.0f

#define NPB 4     // nodes per block (scalar_out / readout) — proven R5
#define NPU 4     // nodes per block (update) — proven R5
#define NGB 4     // nodes per block (aggregate) — proven R5

// ---------- persistent scratch ----------
__device__ float g_ns  [N_NODES * H];
__device__ float g_ns2 [N_NODES * H];
__device__ float g_vecA[N_NODES * 3 * H];
__device__ float g_vecB[N_NODES * 3 * H];
__device__ float g_so  [N_NODES * F3H];

// CSR / sorted edge data (built once per launch)
__device__ int    g_rowptr[N_NODES + 1];
__device__ int    g_cursor[N_NODES];
__device__ int    g_src_s [N_EDGES];
__device__ float4 g_geo_s [N_EDGES];             // {fcut, u0, u1, u2}
__device__ float2 g_trig_s[N_EDGES];             // {2*cos(x), sin(x)/dist} for rbf recurrence

__device__ __forceinline__ float silu_f(float x) {
    return x / (1.0f + expf(-x));
}

// ---------- CSR build ----------
__global__ void k_zero_cnt() {
    int i = blockIdx.x * blockDim.x + threadIdx.x;
    if (i < N_NODES) g_cursor[i] = 0;
}

__global__ void k_hist(const int* __restrict__ edge) {
    int e = blockIdx.x * blockDim.x + threadIdx.x;
    if (e < N_EDGES) atomicAdd(&g_cursor[edge[2 * e]], 1);
}

__global__ void __launch_bounds__(1024) k_scan() {
    __shared__ int s_part[1024];
    int tid = threadIdx.x;
    const int CH = 10;
    int base = tid * CH;
    int local[CH];
    int sum = 0;
#pragma unroll
    for (int i = 0; i < CH; i++) {
        int idx = base + i;
        int v = (idx < N_NODES) ? g_cursor[idx] : 0;
        local[i] = sum;
        sum += v;
    }
    s_part[tid] = sum;
    __syncthreads();
    for (int off = 1; off < 1024; off <<= 1) {
        int add = (tid >= off) ? s_part[tid - off] : 0;
        __syncthreads();
        s_part[tid] += add;
        __syncthreads();
    }
    int excl = (tid > 0) ? s_part[tid - 1] : 0;
#pragma unroll
    for (int i = 0; i < CH; i++) {
        int idx = base + i;
        if (idx < N_NODES) {
            int rp = excl + local[i];
            g_rowptr[idx] = rp;
            g_cursor[idx] = rp;
        }
    }
    if (tid == 0) g_rowptr[N_NODES] = N_EDGES;
}

__global__ void k_scatter(const int* __restrict__ edge,
                          const float* __restrict__ ediff,
                          const float* __restrict__ edist) {
    int e = blockIdx.x * blockDim.x + threadIdx.x;
    if (e >= N_EDGES) return;
    int dst = edge[2 * e], src = edge[2 * e + 1];
    int pos = atomicAdd(&g_cursor[dst], 1);
    g_src_s[pos] = src;
    float dist = edist[e];
    float fcut = (dist < CUTOFF_F) ? 0.5f * (cosf(PI_F * dist / CUTOFF_F) + 1.0f) : 0.0f;
    float inv = 1.0f / dist;
    float4 geo;
    geo.x = fcut;
    geo.y = ediff[3 * e + 0] * inv;
    geo.z = ediff[3 * e + 1] * inv;
    geo.w = ediff[3 * e + 2] * inv;
    g_geo_s[pos] = geo;
    float x = dist * (PI_F / CUTOFF_F);
    float s, c;
    sincosf(x, &s, &c);
    float2 tg;
    tg.x = 2.0f * c;       // recurrence coefficient
    tg.y = s * inv;        // r_1 = sin(x)/dist
    g_trig_s[pos] = tg;
}

// ---------- init ----------
__global__ void __launch_bounds__(H) k_init(const int* __restrict__ z,
                                            const float* __restrict__ embed) {
    int i = blockIdx.x, j = threadIdx.x;
    g_ns[i * H + j] = embed[z[i] * H + j];
#pragma unroll
    for (int d = 0; d < 3; d++) g_vecA[i * 3 * H + d * H + j] = 0.0f;
}

// ---------- scalar_out (R5 exact) ----------
__global__ void __launch_bounds__(H) k_scalar_out(const float* __restrict__ W1,
                                                  const float* __restrict__ b1,
                                                  const float* __restrict__ W2,
                                                  const float* __restrict__ b2) {
    int i0 = blockIdx.x * NPB, j = threadIdx.x;
    __shared__ float s_x[NPB][H];
    __shared__ float s_h[NPB][H];
#pragma unroll
    for (int n = 0; n < NPB; n++) s_x[n][j] = g_ns[(i0 + n) * H + j];
    __syncthreads();

    float acc[NPB];
    float bb = b1[j];
#pragma unroll
    for (int n = 0; n < NPB; n++) acc[n] = bb;
    for (int k = 0; k < H; k++) {
        float w = W1[k * H + j];
#pragma unroll
        for (int n = 0; n < NPB; n++) acc[n] += s_x[n][k] * w;
    }
#pragma unroll
    for (int n = 0; n < NPB; n++) s_h[n][j] = silu_f(acc[n]);
    __syncthreads();

    float a0[NPB], a1[NPB], a2[NPB];
    float c0 = b2[j], c1 = b2[H + j], c2 = b2[2 * H + j];
#pragma unroll
    for (int n = 0; n < NPB; n++) { a0[n] = c0; a1[n] = c1; a2[n] = c2; }
    for (int k = 0; k < H; k++) {
        float w0 = W2[k * F3H + j];
        float w1 = W2[k * F3H + H + j];
        float w2 = W2[k * F3H + 2 * H + j];
#pragma unroll
        for (int n = 0; n < NPB; n++) {
            float h = s_h[n][k];
            a0[n] += h * w0; a1[n] += h * w1; a2[n] += h * w2;
        }
    }
#pragma unroll
    for (int n = 0; n < NPB; n++) {
        g_so[(i0 + n) * F3H + j]         = a0[n];
        g_so[(i0 + n) * F3H + H + j]     = a1[n];
        g_so[(i0 + n) * F3H + 2 * H + j] = a2[n];
    }
}

// ---------- aggregate: R5 structure, rbf via recurrence (fewer regs/loads) ----------
__global__ void __launch_bounds__(H) k_aggregate(const float* __restrict__ Fw,
                                                 const float* __restrict__ Fb) {
    int j = threadIdx.x;

    float rw0[E_RBF], rw1[E_RBF], rw2[E_RBF];
#pragma unroll
    for (int k = 0; k < E_RBF; k++) {
        rw0[k] = Fw[k * F3H + j];
        rw1[k] = Fw[k * F3H + H + j];
        rw2[k] = Fw[k * F3H + 2 * H + j];
    }
    float rb0 = Fb[j], rb1 = Fb[H + j], rb2 = Fb[2 * H + j];

    int n0 = blockIdx.x * NGB;
    for (int n = n0; n < n0 + NGB; n++) {
        int r0 = g_rowptr[n], r1 = g_rowptr[n + 1];
        float accs = 0.0f, av0 = 0.0f, av1 = 0.0f, av2 = 0.0f;
#pragma unroll 2
        for (int p = r0; p < r1; p++) {
            int src = g_src_s[p];
            float4 geo = g_geo_s[p];
            float2 tg = g_trig_s[p];

            // rbf recurrence: r_{k+1} = 2cos(x)*r_k - r_{k-1}, r_1 = sin(x)/d
            float c2 = tg.x;
            float r_p = 0.0f, r_c = tg.y;
            float fw0 = rb0, fw1 = rb1, fw2 = rb2;
#pragma unroll
            for (int k = 0; k < E_RBF; k++) {
                fw0 += r_c * rw0[k];
                fw1 += r_c * rw1[k];
                fw2 += r_c * rw2[k];
                float r_n = c2 * r_c - r_p;
                r_p = r_c;
                r_c = r_n;
            }

            const float* so = g_so + (size_t)src * F3H;
            float fcut = geo.x;
            float gsv = fw0 * (fcut * so[j]);
            float gev = fw1 * (fcut * so[H + j]);
            accs += fw2 * (fcut * so[2 * H + j]);

            const float* vin = g_vecA + (size_t)src * 3 * H;
            av0 += vin[j]         * gsv + gev * geo.y;
            av1 += vin[H + j]     * gsv + gev * geo.z;
            av2 += vin[2 * H + j] * gsv + gev * geo.w;
        }
        g_ns2[(size_t)n * H + j] = g_ns[(size_t)n * H + j] + accs;
        float* vo = g_vecB + (size_t)n * 3 * H;
        const float* va = g_vecA + (size_t)n * 3 * H;
        vo[j]         = va[j]         + av0;
        vo[H + j]     = va[H + j]     + av1;
        vo[2 * H + j] = va[2 * H + j] + av2;
    }
}

// ---------- update (R5 exact, NPU=4) ----------
__global__ void __launch_bounds__(H) k_update(const float* __restrict__ Uw,
                                              const float* __restrict__ Ub,
                                              const float* __restrict__ Vw,
                                              const float* __restrict__ Vb,
                                              const float* __restrict__ W1,
                                              const float* __restrict__ b1,
                                              const float* __restrict__ W2,
                                              const float* __restrict__ b2) {
    int i0 = blockIdx.x * NPU, j = threadIdx.x;
    __shared__ float s_v[NPU][3 * H];
    __shared__ float s_in[NPU][2 * H];
    __shared__ float s_h[NPU][H];

    float ns[NPU];
#pragma unroll
    for (int n = 0; n < NPU; n++) {
#pragma unroll
        for (int d = 0; d < 3; d++)
            s_v[n][d * H + j] = g_vecB[(i0 + n) * 3 * H + d * H + j];
        ns[n] = g_ns2[(i0 + n) * H + j];
        s_in[n][H + j] = ns[n];
    }
    __syncthreads();

    float Uv[NPU][3], Vv[NPU][3];
    float ub = Ub[j], vb = Vb[j];
#pragma unroll
    for (int n = 0; n < NPU; n++)
#pragma unroll
        for (int d = 0; d < 3; d++) { Uv[n][d] = ub; Vv[n][d] = vb; }

    for (int k = 0; k < H; k++) {
        float u = Uw[k * H + j];
        float v = Vw[k * H + j];
#pragma unroll
        for (int n = 0; n < NPU; n++)
#pragma unroll
            for (int d = 0; d < 3; d++) {
                float x = s_v[n][d * H + k];
                Uv[n][d] += x * u;
                Vv[n][d] += x * v;
            }
    }
#pragma unroll
    for (int n = 0; n < NPU; n++)
        s_in[n][j] = sqrtf(Vv[n][0] * Vv[n][0] + Vv[n][1] * Vv[n][1] + Vv[n][2] * Vv[n][2]);
    __syncthreads();

    float acc[NPU];
    float bb = b1[j];
#pragma unroll
    for (int n = 0; n < NPU; n++) acc[n] = bb;
    for (int k = 0; k < 2 * H; k++) {
        float w = W1[k * H + j];
#pragma unroll
        for (int n = 0; n < NPU; n++) acc[n] += s_in[n][k] * w;
    }
#pragma unroll
    for (int n = 0; n < NPU; n++) s_h[n][j] = silu_f(acc[n]);
    __syncthreads();

    float a0[NPU], a1[NPU], a2[NPU];
    float c0 = b2[j], c1 = b2[H + j], c2 = b2[2 * H + j];
#pragma unroll
    for (int n = 0; n < NPU; n++) { a0[n] = c0; a1[n] = c1; a2[n] = c2; }
    for (int k = 0; k < H; k++) {
        float w0 = W2[k * F3H + j];
        float w1 = W2[k * F3H + H + j];
        float w2 = W2[k * F3H + 2 * H + j];
#pragma unroll
        for (int n = 0; n < NPU; n++) {
            float h = s_h[n][k];
            a0[n] += h * w0; a1[n] += h * w1; a2[n] += h * w2;
        }
    }
#pragma unroll
    for (int n = 0; n < NPU; n++) {
        float dot = 0.0f;
#pragma unroll
        for (int d = 0; d < 3; d++) {
            g_vecA[(i0 + n) * 3 * H + d * H + j] = s_v[n][d * H + j] + a0[n] * Uv[n][d];
            dot += Uv[n][d] * Vv[n][d];
        }
        g_ns[(i0 + n) * H + j] = ns[n] + a1[n] * dot + a2[n];
    }
}

// ---------- readout (R5 exact) ----------
__global__ void __launch_bounds__(H) k_readout(const float* __restrict__ W1,
                                               const float* __restrict__ b1,
                                               const float* __restrict__ W2,
                                               const float* __restrict__ b2,
                                               float* __restrict__ out) {
    int i0 = blockIdx.x * NPB, j = threadIdx.x;
    __shared__ float s_x[NPB][H];
    __shared__ float s_h[NPB][H];
#pragma unroll
    for (int n = 0; n < NPB; n++) s_x[n][j] = g_ns[(i0 + n) * H + j];
    __syncthreads();

    float acc[NPB];
    float bb = b1[j];
#pragma unroll
    for (int n = 0; n < NPB; n++) acc[n] = bb;
    for (int k = 0; k < H; k++) {
        float w = W1[k * H + j];
#pragma unroll
        for (int n = 0; n < NPB; n++) acc[n] += s_x[n][k] * w;
    }
#pragma unroll
    for (int n = 0; n < NPB; n++) s_h[n][j] = silu_f(acc[n]);
    __syncthreads();

    float a[NPB];
    float c = b2[j];
#pragma unroll
    for (int n = 0; n < NPB; n++) a[n] = c;
    for (int k = 0; k < H; k++) {
        float w = W2[k * H + j];
#pragma unroll
        for (int n = 0; n < NPB; n++) a[n] += s_h[n][k] * w;
    }
#pragma unroll
    for (int n = 0; n < NPB; n++) out[(i0 + n) * H + j] = a[n];
}

// ---------- host launcher ----------
extern "C" void kernel_launch(void* const* d_in, const int* in_sizes, int n_in,
                              void* d_out, int out_size) {
    const int*   z      = (const int*)  d_in[0];
    const int*   edge   = (const int*)  d_in[1];
    const float* ediff  = (const float*)d_in[2];
    const float* edist  = (const float*)d_in[3];
    const float* embed  = (const float*)d_in[4];
    const float* mfw    = (const float*)d_in[5];
    const float* mfb    = (const float*)d_in[6];
    const float* mw1    = (const float*)d_in[7];
    const float* mb1    = (const float*)d_in[8];
    const float* mw2    = (const float*)d_in[9];
    const float* mb2    = (const float*)d_in[10];
    const float* uUw    = (const float*)d_in[11];
    const float* uUb    = (const float*)d_in[12];
    const float* uVw    = (const float*)d_in[13];
    const float* uVb    = (const float*)d_in[14];
    const float* uw1    = (const float*)d_in[15];
    const float* ub1    = (const float*)d_in[16];
    const float* uw2    = (const float*)d_in[17];
    const float* ub2    = (const float*)d_in[18];
    const float* row1   = (const float*)d_in[19];
    const float* rob1   = (const float*)d_in[20];
    const float* row2   = (const float*)d_in[21];
    const float* rob2   = (const float*)d_in[22];
    float* out = (float*)d_out;

    k_zero_cnt<<<(N_NODES + 255) / 256, 256>>>();
    k_hist<<<(N_EDGES + 255) / 256, 256>>>(edge);
    k_scan<<<1, 1024>>>();
    k_scatter<<<(N_EDGES + 255) / 256, 256>>>(edge, ediff, edist);

    k_init<<<N_NODES, H>>>(z, embed);

    for (int l = 0; l < L_LAYERS; l++) {
        k_scalar_out<<<N_NODES / NPB, H>>>(mw1 + l * H * H, mb1 + l * H,
                                           mw2 + l * H * F3H, mb2 + l * F3H);
        k_aggregate<<<N_NODES / NGB, H>>>(mfw + l * E_RBF * F3H, mfb + l * F3H);
        k_update<<<N_NODES / NPU, H>>>(uUw + l * H * H, uUb + l * H,
                                       uVw + l * H * H, uVb + l * H,
                                       uw1 + l * 2 * H * H, ub1 + l * H,
                                       uw2 + l * H * F3H, ub2 + l * F3H);
    }
    k_readout<<<N_NODES / NPB, H>>>(row1, rob1, row2, rob2, out);
}